// round 1
// baseline (speedup 1.0000x reference)
#include <cuda_runtime.h>
#include <cuda_bf16.h>

// ChamferLoss: N=M=16384 points in 3D.
// loss = mean_i sqrt(min_j d2(x_i,y_j)) + mean_j sqrt(min_i d2(...))
// Inner loop tracks m = min_j (0.5*|y|^2 - x.y); d2 = |x|^2 + 2m.
// Cross-block min combine via atomicMin on float bits (d2 >= 0).

#define NPTS 16384
#define TX 8            // x-points per thread (register tile)
#define BT 128          // threads per block
#define XCHUNK (TX * BT)   // 1024 x-points per block
#define YTILE 1024         // y-points per block (smem tile)
#define XC (NPTS / XCHUNK) // 16
#define YC (NPTS / YTILE)  // 16

__device__ unsigned int g_minbits[2 * NPTS];

__global__ void chamfer_init() {
    int i = blockIdx.x * blockDim.x + threadIdx.x;
    if (i < 2 * NPTS) g_minbits[i] = 0x7f800000u;  // +inf
}

__global__ __launch_bounds__(BT) void chamfer_main(const float* __restrict__ pred,
                                                   const float* __restrict__ gt) {
    const int dir = blockIdx.z;                 // 0: x=pred,y=gt ; 1: x=gt,y=pred
    const float* __restrict__ X = dir ? gt : pred;
    const float* __restrict__ Y = dir ? pred : gt;
    const int xc = blockIdx.x;
    const int yc = blockIdx.y;

    __shared__ float4 sy[YTILE];   // {y0, y1, y2, 0.5*|y|^2}

    // Stage y-tile into shared memory.
    for (int i = threadIdx.x; i < YTILE; i += BT) {
        int p = yc * YTILE + i;
        float y0 = Y[3 * p + 0];
        float y1 = Y[3 * p + 1];
        float y2 = Y[3 * p + 2];
        sy[i] = make_float4(y0, y1, y2, 0.5f * (y0 * y0 + y1 * y1 + y2 * y2));
    }
    __syncthreads();

    // Load TX x-points into registers (strided by BT for coalesced access).
    float x0[TX], x1[TX], x2[TX], mn[TX];
    int pbase = xc * XCHUNK + threadIdx.x;
#pragma unroll
    for (int k = 0; k < TX; ++k) {
        int p = pbase + k * BT;
        x0[k] = X[3 * p + 0];
        x1[k] = X[3 * p + 1];
        x2[k] = X[3 * p + 2];
        mn[k] = __int_as_float(0x7f800000);  // +inf
    }

    // Mainloop: 1 broadcast LDS.128 per y, then TX * (3 FFMA + 1 FMNMX).
#pragma unroll 4
    for (int j = 0; j < YTILE; ++j) {
        float4 y = sy[j];
#pragma unroll
        for (int k = 0; k < TX; ++k) {
            float t = y.w;
            t = fmaf(-x0[k], y.x, t);
            t = fmaf(-x1[k], y.y, t);
            t = fmaf(-x2[k], y.z, t);
            mn[k] = fminf(mn[k], t);
        }
    }

    // Combine: d2 = |x|^2 + 2*m, clamp to 0, atomic-min on bits (deterministic).
#pragma unroll
    for (int k = 0; k < TX; ++k) {
        int p = pbase + k * BT;
        float xsq = x0[k] * x0[k] + x1[k] * x1[k] + x2[k] * x2[k];
        float d2 = fmaxf(fmaf(2.0f, mn[k], xsq), 0.0f);
        atomicMin(&g_minbits[dir * NPTS + p], __float_as_uint(d2));
    }
}

__global__ __launch_bounds__(1024) void chamfer_reduce(float* __restrict__ out) {
    __shared__ float red[1024];
    float s = 0.0f;
    for (int i = threadIdx.x; i < 2 * NPTS; i += 1024)
        s += sqrtf(__uint_as_float(g_minbits[i]));
    red[threadIdx.x] = s;
    __syncthreads();
    for (int w = 512; w > 0; w >>= 1) {
        if (threadIdx.x < w) red[threadIdx.x] += red[threadIdx.x + w];
        __syncthreads();
    }
    if (threadIdx.x == 0) out[0] = red[0] * (1.0f / (float)NPTS);
}

extern "C" void kernel_launch(void* const* d_in, const int* in_sizes, int n_in,
                              void* d_out, int out_size) {
    const float* pred = (const float*)d_in[0];
    const float* gt   = (const float*)d_in[1];
    float* out = (float*)d_out;

    chamfer_init<<<(2 * NPTS + 255) / 256, 256>>>();
    dim3 grid(XC, YC, 2);
    chamfer_main<<<grid, BT>>>(pred, gt);
    chamfer_reduce<<<1, 1024>>>(out);
}

// round 2
// speedup vs baseline: 1.0087x; 1.0087x over previous
#include <cuda_runtime.h>
#include <cuda_bf16.h>

// ChamferLoss: N=M=16384 points in 3D.
// loss = mean_i sqrt(min_j d2) + mean_j sqrt(min_i d2)
// Inner loop tracks m = min_j (0.5*|y|^2 - x.y); d2 = |x|^2 + 2m.
// Round 2: packed fma.rn.f32x2 (FFMA2) — two x-points per FMA instruction.
// y components pre-duplicated in smem as {v,v} pairs so no per-iter packing.

#define NPTS 16384
#define TX 8              // x-points per thread (4 packed pairs)
#define BT 128            // threads per block
#define XCHUNK (TX * BT)  // 1024 x-points per block
#define YTILE 1024        // y-points per block (smem tile)
#define XC (NPTS / XCHUNK)
#define YC (NPTS / YTILE)

__device__ unsigned int g_minbits[2 * NPTS];

__global__ void chamfer_init() {
    int i = blockIdx.x * blockDim.x + threadIdx.x;
    if (i < 2 * NPTS) g_minbits[i] = 0x7f800000u;  // +inf
}

__device__ __forceinline__ unsigned long long pack2(float lo, float hi) {
    unsigned long long r;
    asm("mov.b64 %0, {%1, %2};" : "=l"(r) : "f"(lo), "f"(hi));
    return r;
}

__global__ __launch_bounds__(BT) void chamfer_main(const float* __restrict__ pred,
                                                   const float* __restrict__ gt) {
    const int dir = blockIdx.z;                 // 0: x=pred,y=gt ; 1: x=gt,y=pred
    const float* __restrict__ X = dir ? gt : pred;
    const float* __restrict__ Y = dir ? pred : gt;
    const int xc = blockIdx.x;
    const int yc = blockIdx.y;

    // Per y-point: {y0,y0, y1,y1, y2,y2, w,w}  (w = 0.5*|y|^2), 32 bytes.
    __shared__ float4 sy[YTILE * 2];

    for (int i = threadIdx.x; i < YTILE; i += BT) {
        int p = yc * YTILE + i;
        float y0 = Y[3 * p + 0];
        float y1 = Y[3 * p + 1];
        float y2 = Y[3 * p + 2];
        float w  = 0.5f * (y0 * y0 + y1 * y1 + y2 * y2);
        sy[2 * i + 0] = make_float4(y0, y0, y1, y1);
        sy[2 * i + 1] = make_float4(y2, y2, w, w);
    }
    __syncthreads();

    // Load TX x-points; pack adjacent pairs (negated) for fma.f32x2.
    unsigned long long nx0[TX / 2], nx1[TX / 2], nx2[TX / 2];
    float xsq[TX], mn[TX];
    const int pbase = xc * XCHUNK + threadIdx.x;
#pragma unroll
    for (int g = 0; g < TX / 2; ++g) {
        int pa = pbase + (2 * g + 0) * BT;
        int pb = pbase + (2 * g + 1) * BT;
        float a0 = X[3 * pa + 0], a1 = X[3 * pa + 1], a2 = X[3 * pa + 2];
        float b0 = X[3 * pb + 0], b1 = X[3 * pb + 1], b2 = X[3 * pb + 2];
        nx0[g] = pack2(-a0, -b0);
        nx1[g] = pack2(-a1, -b1);
        nx2[g] = pack2(-a2, -b2);
        xsq[2 * g + 0] = a0 * a0 + a1 * a1 + a2 * a2;
        xsq[2 * g + 1] = b0 * b0 + b1 * b1 + b2 * b2;
        mn[2 * g + 0] = __int_as_float(0x7f800000);
        mn[2 * g + 1] = __int_as_float(0x7f800000);
    }

    const ulonglong2* __restrict__ s2 = (const ulonglong2*)sy;

    // Mainloop: 2 broadcast LDS.128 + per pair-group 3 FFMA2 + 2 FMNMX.
#pragma unroll 2
    for (int j = 0; j < YTILE; ++j) {
        ulonglong2 ya = s2[2 * j + 0];   // {y0p, y1p}
        ulonglong2 yb = s2[2 * j + 1];   // {y2p, wp}
#pragma unroll
        for (int g = 0; g < TX / 2; ++g) {
            unsigned long long t1, t2, t3;
            asm("fma.rn.f32x2 %0, %1, %2, %3;" : "=l"(t1) : "l"(nx0[g]), "l"(ya.x), "l"(yb.y));
            asm("fma.rn.f32x2 %0, %1, %2, %3;" : "=l"(t2) : "l"(nx1[g]), "l"(ya.y), "l"(t1));
            asm("fma.rn.f32x2 %0, %1, %2, %3;" : "=l"(t3) : "l"(nx2[g]), "l"(yb.x), "l"(t2));
            float tlo, thi;
            asm("mov.b64 {%0, %1}, %2;" : "=f"(tlo), "=f"(thi) : "l"(t3));
            mn[2 * g + 0] = fminf(mn[2 * g + 0], tlo);
            mn[2 * g + 1] = fminf(mn[2 * g + 1], thi);
        }
    }

    // Combine: d2 = |x|^2 + 2*m, clamp to 0, atomic-min on bits (deterministic).
#pragma unroll
    for (int k = 0; k < TX; ++k) {
        int p = pbase + k * BT;
        float d2 = fmaxf(fmaf(2.0f, mn[k], xsq[k]), 0.0f);
        atomicMin(&g_minbits[dir * NPTS + p], __float_as_uint(d2));
    }
}

__global__ __launch_bounds__(1024) void chamfer_reduce(float* __restrict__ out) {
    __shared__ float red[1024];
    float s = 0.0f;
    for (int i = threadIdx.x; i < 2 * NPTS; i += 1024)
        s += sqrtf(__uint_as_float(g_minbits[i]));
    red[threadIdx.x] = s;
    __syncthreads();
    for (int w = 512; w > 0; w >>= 1) {
        if (threadIdx.x < w) red[threadIdx.x] += red[threadIdx.x + w];
        __syncthreads();
    }
    if (threadIdx.x == 0) out[0] = red[0] * (1.0f / (float)NPTS);
}

extern "C" void kernel_launch(void* const* d_in, const int* in_sizes, int n_in,
                              void* d_out, int out_size) {
    const float* pred = (const float*)d_in[0];
    const float* gt   = (const float*)d_in[1];
    float* out = (float*)d_out;

    chamfer_init<<<(2 * NPTS + 255) / 256, 256>>>();
    dim3 grid(XC, YC, 2);
    chamfer_main<<<grid, BT>>>(pred, gt);
    chamfer_reduce<<<1, 1024>>>(out);
}